// round 8
// baseline (speedup 1.0000x reference)
#include <cuda_runtime.h>
#include <cuda_bf16.h>
#include <cstdint>

// Problem constants
#define NN 50000
#define EE 500000
#define RR 8
#define HD 128
#define NG 64
#define NC 16
#define NTILES ((NN + 127) / 128)   // 391
#define NBLK ((NN + 255) / 256)     // 196

// ---------------- scratch (device globals; no allocs allowed) ----------------
__device__ __align__(16) __nv_bfloat16 g_xwb[(size_t)NN * 1024];  // messages, bf16
__device__ float g_hacc0[(size_t)NN * HD];     // layer-1 accumulator
__device__ float g_hacc1[(size_t)NN * HD];     // layer-2 accumulator
__device__ __align__(16) __nv_bfloat16 g_wh[9 * 128 * 128];  // weight hi, [ct][n][k]
__device__ __align__(16) __nv_bfloat16 g_wl[9 * 128 * 128];  // weight lo, [ct][n][k]
__device__ int   g_cnt[NN * RR];               // per (dst, rel) counts
__device__ int   g_ncnt[NN];                   // per dst counts
__device__ int   g_off[NN];                    // CSR offsets
__device__ int   g_cur[NN];                    // scatter cursors
__device__ int   g_bsum[256];                  // block sums for scan
__device__ int   g_bbase[256];                 // scanned block bases
__device__ int2  g_edges[EE];                  // dst-sorted: {src*8+rel, coef bits}
__device__ float g_pool[NG * HD];
__device__ float g_pcnt[NG];

// ---------------- helpers ----------------
__device__ __forceinline__ uint32_t smem_to_u32(const void* p) {
    uint32_t a;
    asm("{ .reg .u64 t; cvta.to.shared.u64 t, %1; cvt.u32.u64 %0, t; }" : "=r"(a) : "l"(p));
    return a;
}
__device__ __forceinline__ uint32_t pack_bf2(__nv_bfloat16 a, __nv_bfloat16 b) {
    __nv_bfloat162 t = __halves2bfloat162(a, b);
    return *reinterpret_cast<uint32_t*>(&t);
}
__device__ __forceinline__ void split_bf(float v, __nv_bfloat16& h, __nv_bfloat16& l) {
    h = __float2bfloat16(v);
    l = __float2bfloat16(v - __bfloat162float(h));
}
__device__ __forceinline__ void cp16(uint32_t dst, const void* src) {
    asm volatile("cp.async.cg.shared.global [%0], [%1], 16;" :: "r"(dst), "l"(src));
}
#define CP_COMMIT() asm volatile("cp.async.commit_group;" ::: "memory")
#define CP_WAIT(n)  asm volatile("cp.async.wait_group %0;" :: "n"(n) : "memory")

__device__ __forceinline__ void ldsm_x4(uint32_t addr, uint32_t& r0, uint32_t& r1,
                                        uint32_t& r2, uint32_t& r3) {
    asm volatile("ldmatrix.sync.aligned.m8n8.x4.shared.b16 {%0,%1,%2,%3}, [%4];"
                 : "=r"(r0), "=r"(r1), "=r"(r2), "=r"(r3) : "r"(addr));
}
__device__ __forceinline__ void mma16816(float* c, const uint32_t* a, const uint32_t* b) {
    asm volatile("mma.sync.aligned.m16n8k16.row.col.f32.bf16.bf16.f32 "
                 "{%0,%1,%2,%3}, {%4,%5,%6,%7}, {%8,%9}, {%0,%1,%2,%3};"
                 : "+f"(c[0]), "+f"(c[1]), "+f"(c[2]), "+f"(c[3])
                 : "r"(a[0]), "r"(a[1]), "r"(a[2]), "r"(a[3]), "r"(b[0]), "r"(b[1]));
}

// smem layout (bytes): padded rows 136 bf16 = 272 B; tile = 128*272 = 34816
#define ROWB 272
#define TILEB 34816
#define SM_A_HI 0
#define SM_A_LO 34816
#define SM_BP0  69632               // pair buffer 0 (2 tiles)
#define SM_BP1  139264              // pair buffer 1 (2 tiles)
#define SMEM_TOTAL 208896

// ---------------- structure kernels ----------------
__global__ void zero_kernel() {
    int i = blockIdx.x * blockDim.x + threadIdx.x;
    if (i < NN * RR) g_cnt[i] = 0;
    if (i < NN) g_ncnt[i] = 0;
    if (i < NG * HD) g_pool[i] = 0.0f;
    if (i < NG) g_pcnt[i] = 0.0f;
}
__global__ void count_kernel(const int* __restrict__ dst, const int* __restrict__ rel) {
    int e = blockIdx.x * blockDim.x + threadIdx.x;
    if (e < EE) {
        int d = dst[e];
        atomicAdd(&g_cnt[d * RR + rel[e]], 1);
        atomicAdd(&g_ncnt[d], 1);
    }
}
__global__ void pcnt_kernel(const int* __restrict__ batch) {
    int i = blockIdx.x * blockDim.x + threadIdx.x;
    if (i < NN)
        asm volatile("red.global.add.f32 [%0], %1;" :: "l"(&g_pcnt[batch[i]]), "f"(1.0f) : "memory");
}
__global__ void scan_bsum_kernel() {
    __shared__ int s[256];
    int i = blockIdx.x * 256 + threadIdx.x;
    int t = threadIdx.x;
    s[t] = (i < NN) ? g_ncnt[i] : 0;
    __syncthreads();
    for (int st = 128; st > 0; st >>= 1) {
        if (t < st) s[t] += s[t + st];
        __syncthreads();
    }
    if (t == 0) g_bsum[blockIdx.x] = s[0];
}
__global__ void scan_base_kernel() {   // single block, 256 threads
    __shared__ int s[256];
    int t = threadIdx.x;
    int v = (t < NBLK) ? g_bsum[t] : 0;
    s[t] = v;
    __syncthreads();
    for (int st = 1; st < 256; st <<= 1) {
        int add = (t >= st) ? s[t - st] : 0;
        __syncthreads();
        s[t] += add;
        __syncthreads();
    }
    if (t < NBLK) g_bbase[t] = s[t] - v;
}
__global__ void scan_final_kernel() {
    __shared__ int s[256];
    int i = blockIdx.x * 256 + threadIdx.x;
    int t = threadIdx.x;
    int v = (i < NN) ? g_ncnt[i] : 0;
    s[t] = v;
    __syncthreads();
    for (int st = 1; st < 256; st <<= 1) {
        int add = (t >= st) ? s[t - st] : 0;
        __syncthreads();
        s[t] += add;
        __syncthreads();
    }
    if (i < NN) {
        int off = g_bbase[blockIdx.x] + s[t] - v;
        g_off[i] = off;
        g_cur[i] = off;
    }
}
__global__ void scatter_kernel(const int* __restrict__ src, const int* __restrict__ dst,
                               const int* __restrict__ rel) {
    int e = blockIdx.x * blockDim.x + threadIdx.x;
    if (e >= EE) return;
    int d = dst[e], r = rel[e];
    int c = g_cnt[d * RR + r];
    float coef = 1.0f / (float)max(c, 1);
    int pos = atomicAdd(&g_cur[d], 1);
    g_edges[pos] = make_int2(src[e] * 8 + r, __float_as_int(coef));
}

// pack weights: split fp32 -> bf16 hi/lo, layout [ct][n][k] (col-major for mma row.col)
__global__ void pack_w_kernel(const float* __restrict__ W, const float* __restrict__ root) {
    int i = blockIdx.x * blockDim.x + threadIdx.x;
    if (i >= 9 * 128 * 128) return;
    int ct = i >> 14;
    int rem = i & 16383;
    int n = rem >> 7;
    int k = rem & 127;
    float v = (ct < 8) ? W[((size_t)ct * 128 + k) * 128 + n] : root[(size_t)k * 128 + n];
    __nv_bfloat16 h, l;
    split_bf(v, h, l);
    g_wh[i] = h;
    g_wl[i] = l;
}

// ---------------- mma.sync GEMM: A[M,128] @ Wcat[128,1152] ----------------
// Relation cts processed in pairs (two B tiles resident, one A fragment load
// feeds 32 MMAs). Root ct: fused 3-pass split-bf16 + bias -> hacc.
__global__ __launch_bounds__(256, 1)
void gemm_mma_kernel(const float* __restrict__ x_in, const float* __restrict__ bias, int layer) {
    extern __shared__ char smem[];
    const float* __restrict__ A = (layer == 0) ? x_in : g_hacc0;
    float* __restrict__ outroot = (layer == 0) ? g_hacc0 : g_hacc1;
    const bool relu = (layer != 0);

    const int tid = threadIdx.x;
    const int wid = tid >> 5, lane = tid & 31;
    const int warp_m = wid >> 2;
    const int warp_n = wid & 3;
    const int mt = blockIdx.x;
    const uint32_t su = smem_to_u32(smem);

    const uint32_t a_lane = (uint32_t)(warp_m * 64 + ((lane >> 3) & 1) * 8 + (lane & 7)) * ROWB
                          + (uint32_t)(lane >> 4) * 16;
    const uint32_t b_lane = (uint32_t)(warp_n * 32 + ((lane >> 4) & 1) * 8 + (lane & 7)) * ROWB
                          + (uint32_t)((lane >> 3) & 1) * 16;

    float2 bv[4];
    #pragma unroll
    for (int ni = 0; ni < 4; ni++)
        bv[ni] = *(const float2*)(bias + warp_n * 32 + ni * 8 + (lane & 3) * 2);

    // ---- load + split A tile (once per block) ----
    {
        int row = tid >> 1;
        int kh = (tid & 1) * 64;
        int m = mt * 128 + row;
        const float* ap = A + (size_t)m * 128 + kh;
        char* dh = smem + SM_A_HI + row * ROWB + kh * 2;
        char* dl = smem + SM_A_LO + row * ROWB + kh * 2;
        #pragma unroll
        for (int j = 0; j < 16; j++) {
            float4 v = make_float4(0.f, 0.f, 0.f, 0.f);
            if (m < NN) v = *(const float4*)(ap + 4 * j);
            if (relu) {
                v.x = fmaxf(v.x, 0.f); v.y = fmaxf(v.y, 0.f);
                v.z = fmaxf(v.z, 0.f); v.w = fmaxf(v.w, 0.f);
            }
            __nv_bfloat16 h0, l0, h1, l1, h2, l2, h3, l3;
            split_bf(v.x, h0, l0); split_bf(v.y, h1, l1);
            split_bf(v.z, h2, l2); split_bf(v.w, h3, l3);
            *(uint32_t*)(dh + 8 * j)     = pack_bf2(h0, h1);
            *(uint32_t*)(dh + 8 * j + 4) = pack_bf2(h2, h3);
            *(uint32_t*)(dl + 8 * j)     = pack_bf2(l0, l1);
            *(uint32_t*)(dl + 8 * j + 4) = pack_bf2(l2, l3);
        }
    }

    #define PF_TILE(gsrc, ct_, smoff) do {                                            \
        int n_ = tid >> 1, half_ = tid & 1;                                           \
        const char* s_ = (const char*)((gsrc) + (size_t)(ct_) * 16384 + n_ * 128 + half_ * 64); \
        uint32_t d_ = su + (smoff) + n_ * ROWB + half_ * 128;                         \
        _Pragma("unroll")                                                             \
        for (int j_ = 0; j_ < 8; j_++) cp16(d_ + 16 * j_, s_ + 16 * j_);              \
    } while (0)

    // pair 0 (cts 0,1) into buffer 0
    PF_TILE(g_wh, 0, SM_BP0);
    PF_TILE(g_wh, 1, SM_BP0 + TILEB);
    CP_COMMIT();

    const uint32_t as_h = su + SM_A_HI + a_lane;
    const uint32_t as_l = su + SM_A_LO + a_lane;

    #define LOAD_A4(dst, base, koff) do {                                             \
        _Pragma("unroll")                                                             \
        for (int mi = 0; mi < 4; mi++)                                                \
            ldsm_x4((base) + mi * (16 * ROWB) + (koff),                               \
                    dst[mi][0], dst[mi][1], dst[mi][2], dst[mi][3]);                  \
    } while (0)
    #define LOAD_B4(dst, base, koff) do {                                             \
        _Pragma("unroll")                                                             \
        for (int p = 0; p < 2; p++) {                                                 \
            uint32_t r0, r1, r2, r3;                                                  \
            ldsm_x4((base) + p * (16 * ROWB) + (koff), r0, r1, r2, r3);               \
            dst[2 * p][0] = r0; dst[2 * p][1] = r1;                                   \
            dst[2 * p + 1][0] = r2; dst[2 * p + 1][1] = r3;                           \
        }                                                                             \
    } while (0)

    // epilogue for one relation ct (bf16 messages)
    #define EPI_REL(cacc, ct_) do {                                                   \
        _Pragma("unroll")                                                             \
        for (int mi = 0; mi < 4; mi++) {                                              \
            int row0 = mt * 128 + warp_m * 64 + mi * 16 + (lane >> 2);                \
            int row1 = row0 + 8;                                                      \
            _Pragma("unroll")                                                         \
            for (int ni = 0; ni < 4; ni++) {                                          \
                int col = warp_n * 32 + ni * 8 + (lane & 3) * 2;                      \
                if (row0 < NN)                                                        \
                    *(uint32_t*)(g_xwb + (size_t)row0 * 1024 + (ct_) * 128 + col) =   \
                        pack_bf2(__float2bfloat16(cacc[mi][ni][0]),                   \
                                 __float2bfloat16(cacc[mi][ni][1]));                  \
                if (row1 < NN)                                                        \
                    *(uint32_t*)(g_xwb + (size_t)row1 * 1024 + (ct_) * 128 + col) =   \
                        pack_bf2(__float2bfloat16(cacc[mi][ni][2]),                   \
                                 __float2bfloat16(cacc[mi][ni][3]));                  \
            }                                                                         \
        }                                                                             \
    } while (0)

    // ---- relation pairs ----
    for (int pr = 0; pr < 4; pr++) {
        const uint32_t base = su + ((pr & 1) ? SM_BP1 : SM_BP0);
        const uint32_t other = (pr & 1) ? SM_BP0 : SM_BP1;

        if (pr < 3) {
            PF_TILE(g_wh, 2 * pr + 2, other);
            PF_TILE(g_wh, 2 * pr + 3, other + TILEB);
        } else {
            // root hi + lo into the other buffer
            PF_TILE(g_wh, 8, other);
            PF_TILE(g_wl, 8, other + TILEB);
        }
        CP_COMMIT();
        CP_WAIT(1);
        __syncthreads();

        float c0[4][4][4], c1[4][4][4];
        #pragma unroll
        for (int mi = 0; mi < 4; mi++)
            #pragma unroll
            for (int ni = 0; ni < 4; ni++)
                #pragma unroll
                for (int q = 0; q < 4; q++) { c0[mi][ni][q] = 0.0f; c1[mi][ni][q] = 0.0f; }

        const uint32_t bs0 = base + b_lane;
        const uint32_t bs1 = base + TILEB + b_lane;

        #pragma unroll
        for (int k0 = 0; k0 < 8; k0++) {
            const uint32_t koff = (uint32_t)k0 * 32u;
            uint32_t ah[4][4], b0[4][2], b1[4][2];
            LOAD_A4(ah, as_h, koff);
            LOAD_B4(b0, bs0, koff);
            LOAD_B4(b1, bs1, koff);
            #pragma unroll
            for (int mi = 0; mi < 4; mi++)
                #pragma unroll
                for (int ni = 0; ni < 4; ni++) {
                    mma16816(c0[mi][ni], ah[mi], b0[ni]);
                    mma16816(c1[mi][ni], ah[mi], b1[ni]);
                }
        }

        EPI_REL(c0, 2 * pr);
        EPI_REL(c1, 2 * pr + 1);

        __syncthreads();
    }

    // ---- root ct: 3-pass split-bf16 (buffer = pair slot 0 after pr=3) ----
    {
        CP_WAIT(0);
        __syncthreads();
        const uint32_t bs_h = su + SM_BP0 + b_lane;
        const uint32_t bs_l = su + SM_BP0 + TILEB + b_lane;

        float c[4][4][4];
        #pragma unroll
        for (int mi = 0; mi < 4; mi++)
            #pragma unroll
            for (int ni = 0; ni < 4; ni++)
                #pragma unroll
                for (int q = 0; q < 4; q++) c[mi][ni][q] = 0.0f;

        #pragma unroll
        for (int k0 = 0; k0 < 8; k0++) {
            const uint32_t koff = (uint32_t)k0 * 32u;
            uint32_t ah[4][4], al[4][4], bh[4][2], bl[4][2];
            LOAD_A4(ah, as_h, koff); LOAD_A4(al, as_l, koff);
            LOAD_B4(bh, bs_h, koff); LOAD_B4(bl, bs_l, koff);
            #pragma unroll
            for (int mi = 0; mi < 4; mi++)
                #pragma unroll
                for (int ni = 0; ni < 4; ni++) {
                    mma16816(c[mi][ni], ah[mi], bh[ni]);
                    mma16816(c[mi][ni], ah[mi], bl[ni]);
                    mma16816(c[mi][ni], al[mi], bh[ni]);
                }
        }

        #pragma unroll
        for (int mi = 0; mi < 4; mi++) {
            int row0 = mt * 128 + warp_m * 64 + mi * 16 + (lane >> 2);
            int row1 = row0 + 8;
            #pragma unroll
            for (int ni = 0; ni < 4; ni++) {
                int col = warp_n * 32 + ni * 8 + (lane & 3) * 2;
                if (row0 < NN)
                    *(float2*)(outroot + (size_t)row0 * 128 + col) =
                        make_float2(c[mi][ni][0] + bv[ni].x, c[mi][ni][1] + bv[ni].y);
                if (row1 < NN)
                    *(float2*)(outroot + (size_t)row1 * 128 + col) =
                        make_float2(c[mi][ni][2] + bv[ni].x, c[mi][ni][3] + bv[ni].y);
            }
        }
    }
    #undef LOAD_A4
    #undef LOAD_B4
    #undef EPI_REL
    #undef PF_TILE
}

// ---------------- aggregation: one warp per dst node, no atomics ----------------
__global__ void agg_kernel(const int* __restrict__ batch, int layer) {
    int node = (blockIdx.x * blockDim.x + threadIdx.x) >> 5;
    int lane = threadIdx.x & 31;
    if (node >= NN) return;
    int off = g_off[node];
    int n = g_ncnt[node];

    float ax = 0.f, ay = 0.f, az = 0.f, aw = 0.f;
    for (int i = 0; i < n; i++) {
        int2 er = __ldg(&g_edges[off + i]);
        float coef = __int_as_float(er.y);
        const uint2 raw = *(const uint2*)(g_xwb + (size_t)er.x * 128 + lane * 4);
        float2 p0 = __bfloat1622float2(*reinterpret_cast<const __nv_bfloat162*>(&raw.x));
        float2 p1 = __bfloat1622float2(*reinterpret_cast<const __nv_bfloat162*>(&raw.y));
        ax = fmaf(p0.x, coef, ax);
        ay = fmaf(p0.y, coef, ay);
        az = fmaf(p1.x, coef, az);
        aw = fmaf(p1.y, coef, aw);
    }

    if (layer == 0) {
        float4 h = *(float4*)(g_hacc0 + (size_t)node * 128 + lane * 4);
        h.x += ax; h.y += ay; h.z += az; h.w += aw;
        *(float4*)(g_hacc0 + (size_t)node * 128 + lane * 4) = h;
    } else {
        float4 h = *(float4*)(g_hacc1 + (size_t)node * 128 + lane * 4);
        h.x = fmaxf(h.x + ax, 0.f);
        h.y = fmaxf(h.y + ay, 0.f);
        h.z = fmaxf(h.z + az, 0.f);
        h.w = fmaxf(h.w + aw, 0.f);
        int g = __ldg(&batch[node]);
        float* o = g_pool + (size_t)g * HD + lane * 4;
        asm volatile("red.global.add.v4.f32 [%0], {%1, %2, %3, %4};"
                     :: "l"(o), "f"(h.x), "f"(h.y), "f"(h.z), "f"(h.w) : "memory");
    }
}

// ---------------- head ----------------
__global__ void final_kernel(const float* __restrict__ linW, const float* __restrict__ linb,
                             float* __restrict__ out) {
    int g = blockIdx.x;
    int tid = threadIdx.x;  // 128
    __shared__ float p[HD];
    float cnt = fmaxf(g_pcnt[g], 1.0f);
    p[tid] = g_pool[g * HD + tid] / cnt;
    __syncthreads();
    if (tid < NC) {
        float s = linb[tid];
        #pragma unroll 8
        for (int h = 0; h < HD; h++) s = fmaf(p[h], linW[h * NC + tid], s);
        out[g * NC + tid] = s;
    }
}

// ---------------- launch ----------------
extern "C" void kernel_launch(void* const* d_in, const int* in_sizes, int n_in,
                              void* d_out, int out_size) {
    const float* x     = (const float*)d_in[0];
    const int*   eidx  = (const int*)d_in[1];
    const int*   etype = (const int*)d_in[2];
    const int*   batch = (const int*)d_in[3];
    const float* W1    = (const float*)d_in[4];
    const float* root1 = (const float*)d_in[5];
    const float* b1    = (const float*)d_in[6];
    const float* W2    = (const float*)d_in[7];
    const float* root2 = (const float*)d_in[8];
    const float* b2    = (const float*)d_in[9];
    const float* linW  = (const float*)d_in[10];
    const float* linb  = (const float*)d_in[11];
    float* out = (float*)d_out;

    const int* src = eidx;
    const int* dst = eidx + EE;

    static bool attr_done = false;
    if (!attr_done) {
        cudaFuncSetAttribute(gemm_mma_kernel, cudaFuncAttributeMaxDynamicSharedMemorySize, SMEM_TOTAL);
        attr_done = true;
    }

    int pack_blocks = (9 * 128 * 128 + 255) / 256;
    int agg_blocks = (NN * 32 + 255) / 256;

    // ---- structure phase (once; shared by both layers) ----
    zero_kernel<<<(NN * RR + 255) / 256, 256>>>();
    count_kernel<<<(EE + 255) / 256, 256>>>(dst, etype);
    pcnt_kernel<<<(NN + 255) / 256, 256>>>(batch);
    scan_bsum_kernel<<<NBLK, 256>>>();
    scan_base_kernel<<<1, 256>>>();
    scan_final_kernel<<<NBLK, 256>>>();
    scatter_kernel<<<(EE + 255) / 256, 256>>>(src, dst, etype);
    pack_w_kernel<<<pack_blocks, 256>>>(W1, root1);

    // layer 1
    gemm_mma_kernel<<<NTILES, 256, SMEM_TOTAL>>>(x, b1, 0);
    agg_kernel<<<agg_blocks, 256>>>(batch, 0);

    // layer 2 (relu of layer-1 fused into GEMM A-load; relu+pool fused into agg)
    pack_w_kernel<<<pack_blocks, 256>>>(W2, root2);
    gemm_mma_kernel<<<NTILES, 256, SMEM_TOTAL>>>(x, b2, 1);
    agg_kernel<<<agg_blocks, 256>>>(batch, 1);

    final_kernel<<<NG, 128>>>(linW, linb, out);
}

// round 9
// speedup vs baseline: 1.0338x; 1.0338x over previous
#include <cuda_runtime.h>
#include <cuda_bf16.h>
#include <cstdint>

// Problem constants
#define NN 50000
#define EE 500000
#define RR 8
#define HD 128
#define NG 64
#define NC 16
#define NTILES ((NN + 127) / 128)   // 391
#define NBLK ((NN + 255) / 256)     // 196

// ---------------- scratch (device globals; no allocs allowed) ----------------
__device__ __align__(16) __nv_bfloat16 g_xwb[(size_t)NN * 1024];  // messages, bf16
__device__ float g_hacc0[(size_t)NN * HD];     // layer-1 accumulator
__device__ float g_hacc1[(size_t)NN * HD];     // layer-2 accumulator
__device__ __align__(16) __nv_bfloat16 g_wh[9 * 128 * 128];  // weight hi, [ct][n][k]
__device__ __align__(16) __nv_bfloat16 g_wl[9 * 128 * 128];  // weight lo, [ct][n][k]
__device__ int   g_cnt[NN * RR];               // per (dst, rel) counts
__device__ int   g_ncnt[NN];                   // per dst counts
__device__ int   g_off[NN];                    // CSR offsets
__device__ int   g_cur[NN];                    // scatter cursors
__device__ int   g_bsum[256];                  // block sums for scan
__device__ int   g_bbase[256];                 // scanned block bases
__device__ int2  g_edges[EE];                  // dst-sorted: {src*8+rel, coef bits}
__device__ float g_pool[NG * HD];
__device__ float g_pcnt[NG];

// ---------------- helpers ----------------
__device__ __forceinline__ uint32_t smem_to_u32(const void* p) {
    uint32_t a;
    asm("{ .reg .u64 t; cvta.to.shared.u64 t, %1; cvt.u32.u64 %0, t; }" : "=r"(a) : "l"(p));
    return a;
}
__device__ __forceinline__ uint32_t pack_bf2(__nv_bfloat16 a, __nv_bfloat16 b) {
    __nv_bfloat162 t = __halves2bfloat162(a, b);
    return *reinterpret_cast<uint32_t*>(&t);
}
__device__ __forceinline__ void split_bf(float v, __nv_bfloat16& h, __nv_bfloat16& l) {
    h = __float2bfloat16(v);
    l = __float2bfloat16(v - __bfloat162float(h));
}
__device__ __forceinline__ void cp16(uint32_t dst, const void* src) {
    asm volatile("cp.async.cg.shared.global [%0], [%1], 16;" :: "r"(dst), "l"(src));
}
#define CP_COMMIT() asm volatile("cp.async.commit_group;" ::: "memory")
#define CP_WAIT(n)  asm volatile("cp.async.wait_group %0;" :: "n"(n) : "memory")

__device__ __forceinline__ void ldsm_x4(uint32_t addr, uint32_t& r0, uint32_t& r1,
                                        uint32_t& r2, uint32_t& r3) {
    asm volatile("ldmatrix.sync.aligned.m8n8.x4.shared.b16 {%0,%1,%2,%3}, [%4];"
                 : "=r"(r0), "=r"(r1), "=r"(r2), "=r"(r3) : "r"(addr));
}
__device__ __forceinline__ void mma16816(float* c, const uint32_t* a, const uint32_t* b) {
    asm volatile("mma.sync.aligned.m16n8k16.row.col.f32.bf16.bf16.f32 "
                 "{%0,%1,%2,%3}, {%4,%5,%6,%7}, {%8,%9}, {%0,%1,%2,%3};"
                 : "+f"(c[0]), "+f"(c[1]), "+f"(c[2]), "+f"(c[3])
                 : "r"(a[0]), "r"(a[1]), "r"(a[2]), "r"(a[3]), "r"(b[0]), "r"(b[1]));
}

// smem layout (bytes): padded rows 136 bf16 = 272 B; tile = 128*272 = 34816
#define ROWB 272
#define TILEB 34816
#define SM_A_HI 0
#define SM_A_LO 34816
#define SM_B    69632               // single B buffer
#define SMEM_TOTAL 104448           // fits 2 CTAs/SM

// ---------------- structure kernels ----------------
__global__ void zero_kernel() {
    int i = blockIdx.x * blockDim.x + threadIdx.x;
    if (i < NN * RR) g_cnt[i] = 0;
    if (i < NN) g_ncnt[i] = 0;
    if (i < NG * HD) g_pool[i] = 0.0f;
    if (i < NG) g_pcnt[i] = 0.0f;
}
// counts per (dst,rel), per dst, and per-graph node counts — one kernel
__global__ void count_kernel(const int* __restrict__ dst, const int* __restrict__ rel,
                             const int* __restrict__ batch) {
    int e = blockIdx.x * blockDim.x + threadIdx.x;
    if (e < EE) {
        int d = dst[e];
        atomicAdd(&g_cnt[d * RR + rel[e]], 1);
        atomicAdd(&g_ncnt[d], 1);
    }
    if (e < NN)
        asm volatile("red.global.add.f32 [%0], %1;" :: "l"(&g_pcnt[batch[e]]), "f"(1.0f) : "memory");
}
__global__ void scan_bsum_kernel() {
    __shared__ int s[256];
    int i = blockIdx.x * 256 + threadIdx.x;
    int t = threadIdx.x;
    s[t] = (i < NN) ? g_ncnt[i] : 0;
    __syncthreads();
    for (int st = 128; st > 0; st >>= 1) {
        if (t < st) s[t] += s[t + st];
        __syncthreads();
    }
    if (t == 0) g_bsum[blockIdx.x] = s[0];
}
__global__ void scan_base_kernel() {   // single block, 256 threads
    __shared__ int s[256];
    int t = threadIdx.x;
    int v = (t < NBLK) ? g_bsum[t] : 0;
    s[t] = v;
    __syncthreads();
    for (int st = 1; st < 256; st <<= 1) {
        int add = (t >= st) ? s[t - st] : 0;
        __syncthreads();
        s[t] += add;
        __syncthreads();
    }
    if (t < NBLK) g_bbase[t] = s[t] - v;
}
__global__ void scan_final_kernel() {
    __shared__ int s[256];
    int i = blockIdx.x * 256 + threadIdx.x;
    int t = threadIdx.x;
    int v = (i < NN) ? g_ncnt[i] : 0;
    s[t] = v;
    __syncthreads();
    for (int st = 1; st < 256; st <<= 1) {
        int add = (t >= st) ? s[t - st] : 0;
        __syncthreads();
        s[t] += add;
        __syncthreads();
    }
    if (i < NN) {
        int off = g_bbase[blockIdx.x] + s[t] - v;
        g_off[i] = off;
        g_cur[i] = off;
    }
}
__global__ void scatter_kernel(const int* __restrict__ src, const int* __restrict__ dst,
                               const int* __restrict__ rel) {
    int e = blockIdx.x * blockDim.x + threadIdx.x;
    if (e >= EE) return;
    int d = dst[e], r = rel[e];
    int c = g_cnt[d * RR + r];
    float coef = 1.0f / (float)max(c, 1);
    int pos = atomicAdd(&g_cur[d], 1);
    g_edges[pos] = make_int2(src[e] * 8 + r, __float_as_int(coef));
}

// pack weights: split fp32 -> bf16 hi/lo, layout [ct][n][k] (col-major for mma row.col)
__global__ void pack_w_kernel(const float* __restrict__ W, const float* __restrict__ root) {
    int i = blockIdx.x * blockDim.x + threadIdx.x;
    if (i >= 9 * 128 * 128) return;
    int ct = i >> 14;
    int rem = i & 16383;
    int n = rem >> 7;
    int k = rem & 127;
    float v = (ct < 8) ? W[((size_t)ct * 128 + k) * 128 + n] : root[(size_t)k * 128 + n];
    __nv_bfloat16 h, l;
    split_bf(v, h, l);
    g_wh[i] = h;
    g_wl[i] = l;
}

// ---------------- mma.sync GEMM: A[M,128] @ Wcat[128,1152] ----------------
// Single B buffer, 2 CTAs/SM — cross-CTA overlap hides B fills and syncs.
// Relation cts 0..7: single-pass bf16. Root ct 8: Ah*Bh+Al*Bh then Ah*Bl.
__global__ __launch_bounds__(256, 2)
void gemm_mma_kernel(const float* __restrict__ x_in, const float* __restrict__ bias, int layer) {
    extern __shared__ char smem[];
    const float* __restrict__ A = (layer == 0) ? x_in : g_hacc0;
    float* __restrict__ outroot = (layer == 0) ? g_hacc0 : g_hacc1;
    const bool relu = (layer != 0);

    const int tid = threadIdx.x;
    const int wid = tid >> 5, lane = tid & 31;
    const int warp_m = wid >> 2;
    const int warp_n = wid & 3;
    const int mt = blockIdx.x;
    const uint32_t su = smem_to_u32(smem);

    const uint32_t a_lane = (uint32_t)(warp_m * 64 + ((lane >> 3) & 1) * 8 + (lane & 7)) * ROWB
                          + (uint32_t)(lane >> 4) * 16;
    const uint32_t b_lane = (uint32_t)(warp_n * 32 + ((lane >> 4) & 1) * 8 + (lane & 7)) * ROWB
                          + (uint32_t)((lane >> 3) & 1) * 16;

    float2 bv[4];
    #pragma unroll
    for (int ni = 0; ni < 4; ni++)
        bv[ni] = *(const float2*)(bias + warp_n * 32 + ni * 8 + (lane & 3) * 2);

    // ---- load + split A tile (once per block) ----
    {
        int row = tid >> 1;
        int kh = (tid & 1) * 64;
        int m = mt * 128 + row;
        const float* ap = A + (size_t)m * 128 + kh;
        char* dh = smem + SM_A_HI + row * ROWB + kh * 2;
        char* dl = smem + SM_A_LO + row * ROWB + kh * 2;
        #pragma unroll
        for (int j = 0; j < 16; j++) {
            float4 v = make_float4(0.f, 0.f, 0.f, 0.f);
            if (m < NN) v = *(const float4*)(ap + 4 * j);
            if (relu) {
                v.x = fmaxf(v.x, 0.f); v.y = fmaxf(v.y, 0.f);
                v.z = fmaxf(v.z, 0.f); v.w = fmaxf(v.w, 0.f);
            }
            __nv_bfloat16 h0, l0, h1, l1, h2, l2, h3, l3;
            split_bf(v.x, h0, l0); split_bf(v.y, h1, l1);
            split_bf(v.z, h2, l2); split_bf(v.w, h3, l3);
            *(uint32_t*)(dh + 8 * j)     = pack_bf2(h0, h1);
            *(uint32_t*)(dh + 8 * j + 4) = pack_bf2(h2, h3);
            *(uint32_t*)(dl + 8 * j)     = pack_bf2(l0, l1);
            *(uint32_t*)(dl + 8 * j + 4) = pack_bf2(l2, l3);
        }
    }

    #define PF_TILE(gsrc, ct_) do {                                                   \
        int n_ = tid >> 1, half_ = tid & 1;                                           \
        const char* s_ = (const char*)((gsrc) + (size_t)(ct_) * 16384 + n_ * 128 + half_ * 64); \
        uint32_t d_ = su + SM_B + n_ * ROWB + half_ * 128;                            \
        _Pragma("unroll")                                                             \
        for (int j_ = 0; j_ < 8; j_++) cp16(d_ + 16 * j_, s_ + 16 * j_);              \
        CP_COMMIT();                                                                  \
    } while (0)

    PF_TILE(g_wh, 0);

    const uint32_t as_h = su + SM_A_HI + a_lane;
    const uint32_t as_l = su + SM_A_LO + a_lane;
    const uint32_t bs = su + SM_B + b_lane;

    #define LOAD_A4(dst, base, koff) do {                                             \
        _Pragma("unroll")                                                             \
        for (int mi = 0; mi < 4; mi++)                                                \
            ldsm_x4((base) + mi * (16 * ROWB) + (koff),                               \
                    dst[mi][0], dst[mi][1], dst[mi][2], dst[mi][3]);                  \
    } while (0)
    #define LOAD_B4(dst, base, koff) do {                                             \
        _Pragma("unroll")                                                             \
        for (int p = 0; p < 2; p++) {                                                 \
            uint32_t r0, r1, r2, r3;                                                  \
            ldsm_x4((base) + p * (16 * ROWB) + (koff), r0, r1, r2, r3);               \
            dst[2 * p][0] = r0; dst[2 * p][1] = r1;                                   \
            dst[2 * p + 1][0] = r2; dst[2 * p + 1][1] = r3;                           \
        }                                                                             \
    } while (0)

    // ---- relation cts 0..7: single-pass bf16 ----
    for (int ct = 0; ct < 8; ct++) {
        CP_WAIT(0);
        __syncthreads();

        float c[4][4][4];
        #pragma unroll
        for (int mi = 0; mi < 4; mi++)
            #pragma unroll
            for (int ni = 0; ni < 4; ni++)
                #pragma unroll
                for (int q = 0; q < 4; q++) c[mi][ni][q] = 0.0f;

        #pragma unroll
        for (int k0 = 0; k0 < 8; k0++) {
            const uint32_t koff = (uint32_t)k0 * 32u;
            uint32_t ah[4][4], bh[4][2];
            LOAD_A4(ah, as_h, koff);
            LOAD_B4(bh, bs, koff);
            #pragma unroll
            for (int mi = 0; mi < 4; mi++)
                #pragma unroll
                for (int ni = 0; ni < 4; ni++)
                    mma16816(c[mi][ni], ah[mi], bh[ni]);
        }

        // epilogue: bf16 messages (does not touch B smem)
        #pragma unroll
        for (int mi = 0; mi < 4; mi++) {
            int row0 = mt * 128 + warp_m * 64 + mi * 16 + (lane >> 2);
            int row1 = row0 + 8;
            #pragma unroll
            for (int ni = 0; ni < 4; ni++) {
                int col = warp_n * 32 + ni * 8 + (lane & 3) * 2;
                if (row0 < NN)
                    *(uint32_t*)(g_xwb + (size_t)row0 * 1024 + ct * 128 + col) =
                        pack_bf2(__float2bfloat16(c[mi][ni][0]), __float2bfloat16(c[mi][ni][1]));
                if (row1 < NN)
                    *(uint32_t*)(g_xwb + (size_t)row1 * 1024 + ct * 128 + col) =
                        pack_bf2(__float2bfloat16(c[mi][ni][2]), __float2bfloat16(c[mi][ni][3]));
            }
        }

        __syncthreads();        // all warps done reading B
        PF_TILE(g_wh, ct + 1);  // ct==7 prefetches root hi
    }

    // ---- root ct: split-precision in two B phases ----
    {
        float c[4][4][4];
        #pragma unroll
        for (int mi = 0; mi < 4; mi++)
            #pragma unroll
            for (int ni = 0; ni < 4; ni++)
                #pragma unroll
                for (int q = 0; q < 4; q++) c[mi][ni][q] = 0.0f;

        // phase 1: B = root hi;  c += Ah*Bh + Al*Bh
        CP_WAIT(0);
        __syncthreads();
        #pragma unroll
        for (int k0 = 0; k0 < 8; k0++) {
            const uint32_t koff = (uint32_t)k0 * 32u;
            uint32_t ah[4][4], al[4][4], bh[4][2];
            LOAD_A4(ah, as_h, koff);
            LOAD_A4(al, as_l, koff);
            LOAD_B4(bh, bs, koff);
            #pragma unroll
            for (int mi = 0; mi < 4; mi++)
                #pragma unroll
                for (int ni = 0; ni < 4; ni++) {
                    mma16816(c[mi][ni], ah[mi], bh[ni]);
                    mma16816(c[mi][ni], al[mi], bh[ni]);
                }
        }
        __syncthreads();
        PF_TILE(g_wl, 8);

        // phase 2: B = root lo;  c += Ah*Bl
        CP_WAIT(0);
        __syncthreads();
        #pragma unroll
        for (int k0 = 0; k0 < 8; k0++) {
            const uint32_t koff = (uint32_t)k0 * 32u;
            uint32_t ah[4][4], bl[4][2];
            LOAD_A4(ah, as_h, koff);
            LOAD_B4(bl, bs, koff);
            #pragma unroll
            for (int mi = 0; mi < 4; mi++)
                #pragma unroll
                for (int ni = 0; ni < 4; ni++)
                    mma16816(c[mi][ni], ah[mi], bl[ni]);
        }

        // epilogue: fp32 + bias
        #pragma unroll
        for (int mi = 0; mi < 4; mi++) {
            int row0 = mt * 128 + warp_m * 64 + mi * 16 + (lane >> 2);
            int row1 = row0 + 8;
            #pragma unroll
            for (int ni = 0; ni < 4; ni++) {
                int col = warp_n * 32 + ni * 8 + (lane & 3) * 2;
                if (row0 < NN)
                    *(float2*)(outroot + (size_t)row0 * 128 + col) =
                        make_float2(c[mi][ni][0] + bv[ni].x, c[mi][ni][1] + bv[ni].y);
                if (row1 < NN)
                    *(float2*)(outroot + (size_t)row1 * 128 + col) =
                        make_float2(c[mi][ni][2] + bv[ni].x, c[mi][ni][3] + bv[ni].y);
            }
        }
    }
    #undef LOAD_A4
    #undef LOAD_B4
    #undef PF_TILE
}

// ---------------- aggregation: one warp per dst node, no atomics ----------------
__global__ void agg_kernel(const int* __restrict__ batch, int layer) {
    int node = (blockIdx.x * blockDim.x + threadIdx.x) >> 5;
    int lane = threadIdx.x & 31;
    if (node >= NN) return;
    int off = g_off[node];
    int n = g_ncnt[node];

    float ax = 0.f, ay = 0.f, az = 0.f, aw = 0.f;
    for (int i = 0; i < n; i++) {
        int2 er = __ldg(&g_edges[off + i]);
        float coef = __int_as_float(er.y);
        const uint2 raw = *(const uint2*)(g_xwb + (size_t)er.x * 128 + lane * 4);
        float2 p0 = __bfloat1622float2(*reinterpret_cast<const __nv_bfloat162*>(&raw.x));
        float2 p1 = __bfloat1622float2(*reinterpret_cast<const __nv_bfloat162*>(&raw.y));
        ax = fmaf(p0.x, coef, ax);
        ay = fmaf(p0.y, coef, ay);
        az = fmaf(p1.x, coef, az);
        aw = fmaf(p1.y, coef, aw);
    }

    if (layer == 0) {
        float4 h = *(float4*)(g_hacc0 + (size_t)node * 128 + lane * 4);
        h.x += ax; h.y += ay; h.z += az; h.w += aw;
        *(float4*)(g_hacc0 + (size_t)node * 128 + lane * 4) = h;
    } else {
        float4 h = *(float4*)(g_hacc1 + (size_t)node * 128 + lane * 4);
        h.x = fmaxf(h.x + ax, 0.f);
        h.y = fmaxf(h.y + ay, 0.f);
        h.z = fmaxf(h.z + az, 0.f);
        h.w = fmaxf(h.w + aw, 0.f);
        int g = __ldg(&batch[node]);
        float* o = g_pool + (size_t)g * HD + lane * 4;
        asm volatile("red.global.add.v4.f32 [%0], {%1, %2, %3, %4};"
                     :: "l"(o), "f"(h.x), "f"(h.y), "f"(h.z), "f"(h.w) : "memory");
    }
}

// ---------------- head ----------------
__global__ void final_kernel(const float* __restrict__ linW, const float* __restrict__ linb,
                             float* __restrict__ out) {
    int g = blockIdx.x;
    int tid = threadIdx.x;  // 128
    __shared__ float p[HD];
    float cnt = fmaxf(g_pcnt[g], 1.0f);
    p[tid] = g_pool[g * HD + tid] / cnt;
    __syncthreads();
    if (tid < NC) {
        float s = linb[tid];
        #pragma unroll 8
        for (int h = 0; h < HD; h++) s = fmaf(p[h], linW[h * NC + tid], s);
        out[g * NC + tid] = s;
    }
}

// ---------------- launch ----------------
extern "C" void kernel_launch(void* const* d_in, const int* in_sizes, int n_in,
                              void* d_out, int out_size) {
    const float* x     = (const float*)d_in[0];
    const int*   eidx  = (const int*)d_in[1];
    const int*   etype = (const int*)d_in[2];
    const int*   batch = (const int*)d_in[3];
    const float* W1    = (const float*)d_in[4];
    const float* root1 = (const float*)d_in[5];
    const float* b1    = (const float*)d_in[6];
    const float* W2    = (const float*)d_in[7];
    const float* root2 = (const float*)d_in[8];
    const float* b2    = (const float*)d_in[9];
    const float* linW  = (const float*)d_in[10];
    const float* linb  = (const float*)d_in[11];
    float* out = (float*)d_out;

    const int* src = eidx;
    const int* dst = eidx + EE;

    static bool attr_done = false;
    if (!attr_done) {
        cudaFuncSetAttribute(gemm_mma_kernel, cudaFuncAttributeMaxDynamicSharedMemorySize, SMEM_TOTAL);
        attr_done = true;
    }

    int pack_blocks = (9 * 128 * 128 + 255) / 256;
    int agg_blocks = (NN * 32 + 255) / 256;

    // ---- structure phase (once; shared by both layers) ----
    zero_kernel<<<(NN * RR + 255) / 256, 256>>>();
    count_kernel<<<(EE + 255) / 256, 256>>>(dst, etype, batch);
    scan_bsum_kernel<<<NBLK, 256>>>();
    scan_base_kernel<<<1, 256>>>();
    scan_final_kernel<<<NBLK, 256>>>();
    scatter_kernel<<<(EE + 255) / 256, 256>>>(src, dst, etype);
    pack_w_kernel<<<pack_blocks, 256>>>(W1, root1);

    // layer 1
    gemm_mma_kernel<<<NTILES, 256, SMEM_TOTAL>>>(x, b1, 0);
    agg_kernel<<<agg_blocks, 256>>>(batch, 0);

    // layer 2 (relu of layer-1 fused into GEMM A-load; relu+pool fused into agg)
    pack_w_kernel<<<pack_blocks, 256>>>(W2, root2);
    gemm_mma_kernel<<<NTILES, 256, SMEM_TOTAL>>>(x, b2, 1);
    agg_kernel<<<agg_blocks, 256>>>(batch, 1);

    final_kernel<<<NG, 128>>>(linW, linb, out);
}